// round 15
// baseline (speedup 1.0000x reference)
#include <cuda_runtime.h>
#include <cuda_fp16.h>
#include <stdint.h>
#include <math.h>

#define BB 64
#define TT 800
#define EE 1024
#define DD 1024
#define DEDIM 256
#define AA 256
#define VV 8000
#define LL 150
#define KI 1280          // DE + E
#define NG 4096          // 4*D
#define KC 2048          // D + E
#define KG 2304          // DE + E + D
#define GSPLIT 8
#define LSPLIT 8
#define GCH (KG / GSPLIT / 16)            // 18 chunks / gates job
#define LCH (KC / LSPLIT / 16)            // 16 chunks / logits job
#define NJ_GATES (GSPLIT * (NG / 128))    // 256
#define NJ_LOGITS (LSPLIT * 63)           // 504
#define NJ_CTX 256
#define NJ_COMP 1600
#define NST 3                              // cp.async pipeline stages

// ---------------- device scratch (static, allocation-free) ----------------
__device__ __align__(128) __half g_comp16[(size_t)BB * TT * AA];  // 26.2 MB fp16 comp_enc
__device__ __align__(128) __half g_lf16[(size_t)BB * TT * EE];    // 104.9 MB fp16 listener
__device__ __align__(128) float g_WT[(size_t)KG * NG];            // 37.7 MB k-major gates W
__device__ __align__(128) float g_h[2][BB * DD];
__device__ __align__(128) float g_c[BB * DD];
__device__ __align__(128) float g_ctxp[2][4][BB * EE];            // split-T ctx partials
__device__ __align__(128) float g_gp[GSPLIT * BB * NG];
__device__ __align__(128) float g_lp[LSPLIT * BB * VV];
__device__ __align__(128) float g_attn[BB * TT];
__device__ unsigned g_cnt = 0;
__device__ unsigned g_gen = 0;
__device__ unsigned g_jq[3] = {0, 0, 0};

struct Params {
    const float *lf, *emb, *W_ih, *W_hh, *b_ih, *b_hh, *phi, *psi, *bpsi, *Wc, *bc;
    const int *state_len, *tokens;
    float* out;
    unsigned nblk;
};

struct SGEM { float As[NST][16][68]; float Bs[NST][16][132]; };   // 38.4 KB
struct SATT { float hs[DD]; float qs[AA]; float en[TT]; float red[256]; };
union Smem { SGEM g; SATT a; };

__device__ __forceinline__ float sigf(float x) { return 1.0f / (1.0f + expf(-x)); }

__device__ __forceinline__ void cp16(uint32_t d, const void* s) {
    asm volatile("cp.async.cg.shared.global [%0], [%1], 16;" :: "r"(d), "l"(s));
}
#define CP_COMMIT() asm volatile("cp.async.commit_group;")
#define CP_WAIT1()  asm volatile("cp.async.wait_group 1;")

// ---- packed fp32x2 FMA helpers (bitwise == 2x scalar FFMA rn) ----
__device__ __forceinline__ void fma2(unsigned long long& acc, unsigned long long a,
                                     unsigned long long b) {
    asm("fma.rn.f32x2 %0, %1, %2, %0;" : "+l"(acc) : "l"(a), "l"(b));
}
__device__ __forceinline__ unsigned long long dupf(float x) {
    unsigned long long r;
    asm("mov.b64 %0, {%1, %1};" : "=l"(r) : "f"(x));
    return r;
}
__device__ __forceinline__ float2 unpk(unsigned long long v) {
    float2 r;
    asm("mov.b64 {%0, %1}, %2;" : "=f"(r.x), "=f"(r.y) : "l"(v));
    return r;
}

// ---------------- grid barrier; releaser resets selected job counters ------
__device__ __forceinline__ void gsync(unsigned nblk, int rmask) {
    __threadfence();
    __syncthreads();
    if (threadIdx.x == 0) {
        unsigned gen = *(volatile unsigned*)&g_gen;
        if (atomicAdd(&g_cnt, 1u) == nblk - 1u) {
            g_cnt = 0;
            if (rmask & 1) g_jq[0] = 0;
            if (rmask & 2) g_jq[1] = 0;
            if (rmask & 4) g_jq[2] = 0;
            __threadfence();
            atomicAdd(&g_gen, 1u);
        } else {
            while (*(volatile unsigned*)&g_gen == gen) { __nanosleep(32); }
        }
    }
    __syncthreads();
    __threadfence();
}

// ---- ctx read = sum of 4 split-T partials (L2-resident, deterministic order) ----
__device__ __forceinline__ float4 ctx_sum(int par, int idx) {
    float4 a = *(const float4*)&g_ctxp[par][0][idx];
    float4 b = *(const float4*)&g_ctxp[par][1][idx];
    float4 c = *(const float4*)&g_ctxp[par][2][idx];
    float4 d = *(const float4*)&g_ctxp[par][3][idx];
    return make_float4((a.x + b.x) + (c.x + d.x), (a.y + b.y) + (c.y + d.y),
                       (a.z + b.z) + (c.z + d.z), (a.w + b.w) + (c.w + d.w));
}

// ------------- 64x128 tile core, packed f32x2: 4 rows x 4 col-pairs --------
__device__ __forceinline__ void mma16(const float (*As)[68], const float (*Bs)[132],
                                      unsigned long long (&acc)[4][4], int tx, int ty) {
#pragma unroll
    for (int kk = 0; kk < 16; kk++) {
        float4 a = *(const float4*)&As[kk][ty * 4];
        ulonglong2 bl = *(const ulonglong2*)&Bs[kk][tx * 4];
        ulonglong2 bh = *(const ulonglong2*)&Bs[kk][64 + tx * 4];
        unsigned long long ap[4] = {dupf(a.x), dupf(a.y), dupf(a.z), dupf(a.w)};
#pragma unroll
        for (int i = 0; i < 4; i++) {
            fma2(acc[i][0], ap[i], bl.x);
            fma2(acc[i][1], ap[i], bl.y);
            fma2(acc[i][2], ap[i], bh.x);
            fma2(acc[i][3], ap[i], bh.y);
        }
    }
}

// ================= 3-stage pipelined tile bodies =================

__device__ __forceinline__ float4 ld_gates_a(const Params& p, int par, int am,
                                             int tok, int k) {
    if (k < DEDIM) return *(const float4*)&p.emb[(size_t)tok * DEDIM + k];
    if (k < KI)    return ctx_sum(par, am * EE + (k - DEDIM));
    return *(const float4*)&g_h[par][am * DD + (k - KI)];
}

__device__ __forceinline__ void stA(float (*As)[68], int akq, int am, float4 v) {
    As[akq + 0][am] = v.x; As[akq + 1][am] = v.y;
    As[akq + 2][am] = v.z; As[akq + 3][am] = v.w;
}

__device__ void gates_tile(SGEM& s, const Params& p, int job, int t, int pp) {
    int z = job >> 5, nt = job & 31;
    int j0 = nt * 128;
    int kbeg = z * (KG / GSPLIT);
    int tid = threadIdx.x, tx = tid & 15, ty = tid >> 4;
    int am = tid >> 2, akq = (tid & 3) * 4;
    int bk0 = tid >> 5, bn0 = (tid & 31) * 4;
    int tok = p.tokens[am * LL + t];
    uint32_t sB[NST];
#pragma unroll
    for (int u = 0; u < NST; u++)
        sB[u] = (uint32_t)__cvta_generic_to_shared(&s.Bs[u][bk0][bn0]);
    const size_t brow8 = (size_t)8 * NG;
    unsigned long long acc[4][4] = {};
#pragma unroll
    for (int u = 0; u < 2; u++) {
        stA(s.As[u], akq, am, ld_gates_a(p, pp, am, tok, kbeg + u * 16 + akq));
        const float* w = &g_WT[(size_t)(kbeg + u * 16 + bk0) * NG + j0 + bn0];
        cp16(sB[u], w);
        cp16(sB[u] + 8 * 132 * 4, w + brow8);
        CP_COMMIT();
    }
    float4 areg = ld_gates_a(p, pp, am, tok, kbeg + 32 + akq);
    for (int kt = 0; kt < GCH; kt++) {
        int cur = kt % NST, nx2 = (kt + 2) % NST;
        CP_WAIT1();
        __syncthreads();
        if (kt + 2 < GCH) {
            stA(s.As[nx2], akq, am, areg);
            const float* w = &g_WT[(size_t)(kbeg + (kt + 2) * 16 + bk0) * NG + j0 + bn0];
            cp16(sB[nx2], w);
            cp16(sB[nx2] + 8 * 132 * 4, w + brow8);
        }
        CP_COMMIT();
        if (kt + 3 < GCH)
            areg = ld_gates_a(p, pp, am, tok, kbeg + (kt + 3) * 16 + akq);
        mma16(s.As[cur], s.Bs[cur], acc, tx, ty);
    }
#pragma unroll
    for (int i = 0; i < 4; i++) {
        int b = ty * 4 + i;
        float* dst = &g_gp[(size_t)(z * BB + b) * NG + j0];
        float2 p0 = unpk(acc[i][0]), p1 = unpk(acc[i][1]);
        float2 p2 = unpk(acc[i][2]), p3 = unpk(acc[i][3]);
        *(float4*)(dst + tx * 4)      = make_float4(p0.x, p0.y, p1.x, p1.y);
        *(float4*)(dst + 64 + tx * 4) = make_float4(p2.x, p2.y, p3.x, p3.y);
    }
}

__device__ __forceinline__ float4 ld_logits_a(int par, int am, int k) {
    if (k < DD) return *(const float4*)&g_h[par][am * DD + k];
    return ctx_sum(par, am * EE + (k - DD));
}

__device__ void logits_tile(SGEM& s, const Params& p, int job, int pl) {
    int z = job / 63;
    int nt = job - z * 63;
    int v0 = nt * 128;
    bool full = (nt < 62);
    int kbeg = z * (KC / LSPLIT);
    int tid = threadIdx.x, tx = tid & 15, ty = tid >> 4;
    int am = tid >> 2, akq = (tid & 3) * 4;
    int bk0 = tid >> 5, bn0 = (tid & 31) * 4;
    int c0 = v0 + bn0;        if (c0 > VV - 4) c0 = VV - 4;   // clamp: only feeds discarded cols
    uint32_t sB[NST];
#pragma unroll
    for (int u = 0; u < NST; u++)
        sB[u] = (uint32_t)__cvta_generic_to_shared(&s.Bs[u][bk0][bn0]);
    unsigned long long acc[4][4] = {};
#pragma unroll
    for (int u = 0; u < 2; u++) {
        stA(s.As[u], akq, am, ld_logits_a(pl, am, kbeg + u * 16 + akq));
        const float* w0 = &p.Wc[(size_t)(kbeg + u * 16 + bk0) * VV];
        cp16(sB[u], w0 + c0);
        cp16(sB[u] + 8 * 132 * 4, w0 + (size_t)8 * VV + c0);
        CP_COMMIT();
    }
    float4 areg = ld_logits_a(pl, am, kbeg + 32 + akq);
    for (int kt = 0; kt < LCH; kt++) {
        int cur = kt % NST, nx2 = (kt + 2) % NST;
        CP_WAIT1();
        __syncthreads();
        if (kt + 2 < LCH) {
            stA(s.As[nx2], akq, am, areg);
            const float* w0 = &p.Wc[(size_t)(kbeg + (kt + 2) * 16 + bk0) * VV];
            cp16(sB[nx2], w0 + c0);
            cp16(sB[nx2] + 8 * 132 * 4, w0 + (size_t)8 * VV + c0);
        }
        CP_COMMIT();
        if (kt + 3 < LCH)
            areg = ld_logits_a(pl, am, kbeg + (kt + 3) * 16 + akq);
        mma16(s.As[cur], s.Bs[cur], acc, tx, ty);
    }
#pragma unroll
    for (int i = 0; i < 4; i++) {
        int b = ty * 4 + i;
        float* dst = &g_lp[(size_t)(z * BB + b) * VV + v0];
        float2 p0 = unpk(acc[i][0]), p1 = unpk(acc[i][1]);
        *(float4*)(dst + tx * 4) = make_float4(p0.x, p0.y, p1.x, p1.y);
        if (full) {
            float2 p2 = unpk(acc[i][2]), p3 = unpk(acc[i][3]);
            *(float4*)(dst + 64 + tx * 4) = make_float4(p2.x, p2.y, p3.x, p3.y);
        }
    }
}

__device__ void comp_tile(SGEM& s, const Params& p, int job) {
    int nt = job & 1, mt = job >> 1;
    int m0 = mt * 64, n0 = nt * 128;
    int tid = threadIdx.x, tx = tid & 15, ty = tid >> 4;
    int am = tid >> 2, akq = (tid & 3) * 4;
    int bk0 = tid >> 5, bn0 = (tid & 31) * 4;
    uint32_t sB[NST];
#pragma unroll
    for (int u = 0; u < NST; u++)
        sB[u] = (uint32_t)__cvta_generic_to_shared(&s.Bs[u][bk0][bn0]);
    const float* arow = p.lf + (size_t)(m0 + am) * EE;
    unsigned long long acc[4][4] = {};
#pragma unroll
    for (int u = 0; u < 2; u++) {
        stA(s.As[u], akq, am, *(const float4*)&arow[u * 16 + akq]);
        const float* w = &p.psi[(size_t)(u * 16 + bk0) * AA + n0 + bn0];
        cp16(sB[u], w);
        cp16(sB[u] + 8 * 132 * 4, w + (size_t)8 * AA);
        CP_COMMIT();
    }
    float4 areg = *(const float4*)&arow[32 + akq];
    const int NCH = EE / 16;
    for (int kt = 0; kt < NCH; kt++) {
        int cur = kt % NST, nx2 = (kt + 2) % NST;
        CP_WAIT1();
        __syncthreads();
        if (kt + 2 < NCH) {
            stA(s.As[nx2], akq, am, areg);
            const float* w = &p.psi[(size_t)((kt + 2) * 16 + bk0) * AA + n0 + bn0];
            cp16(sB[nx2], w);
            cp16(sB[nx2] + 8 * 132 * 4, w + (size_t)8 * AA);
        }
        CP_COMMIT();
        if (kt + 3 < NCH) areg = *(const float4*)&arow[(kt + 3) * 16 + akq];
        mma16(s.As[cur], s.Bs[cur], acc, tx, ty);
    }
#pragma unroll
    for (int i = 0; i < 4; i++) {
        int m = m0 + ty * 4 + i;
        int nA = n0 + tx * 4, nB = n0 + 64 + tx * 4;
        float2 p0 = unpk(acc[i][0]), p1 = unpk(acc[i][1]);
        float2 p2 = unpk(acc[i][2]), p3 = unpk(acc[i][3]);
        __half2* oA = (__half2*)&g_comp16[(size_t)m * AA + nA];
        __half2* oB = (__half2*)&g_comp16[(size_t)m * AA + nB];
        oA[0] = __floats2half2_rn(tanhf(p0.x + p.bpsi[nA + 0]), tanhf(p0.y + p.bpsi[nA + 1]));
        oA[1] = __floats2half2_rn(tanhf(p1.x + p.bpsi[nA + 2]), tanhf(p1.y + p.bpsi[nA + 3]));
        oB[0] = __floats2half2_rn(tanhf(p2.x + p.bpsi[nB + 0]), tanhf(p2.y + p.bpsi[nB + 1]));
        oB[1] = __floats2half2_rn(tanhf(p3.x + p.bpsi[nB + 2]), tanhf(p3.y + p.bpsi[nB + 3]));
    }
}

// lstm + q + energy + masked softmax for batch row b (one block)
__device__ void lstm_attn(SATT& a, const Params& p, int b, int t) {
    int tid = threadIdx.x;
    int pt = t & 1;
#pragma unroll
    for (int i = 0; i < 4; i++) {
        int d = tid + i * 256;
        int g = b * DD + d;
        float gv[4];
#pragma unroll
        for (int q = 0; q < 4; q++) {
            int j = q * DD + d;
            float s = p.b_ih[j] + p.b_hh[j];
#pragma unroll
            for (int z = 0; z < GSPLIT; z++) s += g_gp[(size_t)(z * BB + b) * NG + j];
            gv[q] = s;
        }
        float cn = sigf(gv[1]) * g_c[g] + sigf(gv[0]) * tanhf(gv[2]);
        g_c[g] = cn;
        float hn = sigf(gv[3]) * tanhf(cn);
        g_h[pt][g] = hn;
        a.hs[d] = hn;
    }
    __syncthreads();
    {
        float acc0 = 0.f, acc1 = 0.f, acc2 = 0.f, acc3 = 0.f;
        const float* ph = p.phi + tid;
        for (int k = 0; k < DD; k += 4) {
            acc0 += a.hs[k]     * ph[0];
            acc1 += a.hs[k + 1] * ph[AA];
            acc2 += a.hs[k + 2] * ph[2 * AA];
            acc3 += a.hs[k + 3] * ph[3 * AA];
            ph += 4 * AA;
        }
        a.qs[tid] = tanhf((acc0 + acc1) + (acc2 + acc3));
    }
    __syncthreads();
    int w = tid >> 5, lane = tid & 31;
    float4 q0 = *(const float4*)&a.qs[lane * 8];
    float4 q1 = *(const float4*)&a.qs[lane * 8 + 4];
    for (int tb = w; tb < TT; tb += 16) {
        int ta = tb, tc = tb + 8;
        uint4 ua = *(const uint4*)(g_comp16 + ((size_t)b * TT + ta) * AA + lane * 8);
        uint4 uc = *(const uint4*)(g_comp16 + ((size_t)b * TT + tc) * AA + lane * 8);
        float2 x0 = __half22float2(*(__half2*)&ua.x);
        float2 x1 = __half22float2(*(__half2*)&ua.y);
        float2 x2 = __half22float2(*(__half2*)&ua.z);
        float2 x3 = __half22float2(*(__half2*)&ua.w);
        float2 y0 = __half22float2(*(__half2*)&uc.x);
        float2 y1 = __half22float2(*(__half2*)&uc.y);
        float2 y2 = __half22float2(*(__half2*)&uc.z);
        float2 y3 = __half22float2(*(__half2*)&uc.w);
        float sa = x0.x * q0.x + x0.y * q0.y + x1.x * q0.z + x1.y * q0.w
                 + x2.x * q1.x + x2.y * q1.y + x3.x * q1.z + x3.y * q1.w;
        float sc = y0.x * q0.x + y0.y * q0.y + y1.x * q0.z + y1.y * q0.w
                 + y2.x * q1.x + y2.y * q1.y + y3.x * q1.z + y3.y * q1.w;
#pragma unroll
        for (int o = 16; o > 0; o >>= 1) {
            sa += __shfl_down_sync(0xffffffffu, sa, o);
            sc += __shfl_down_sync(0xffffffffu, sc, o);
        }
        if (lane == 0) { a.en[ta] = 2.0f * sa; a.en[tc] = 2.0f * sc; }
    }
    __syncthreads();
    int sl = p.state_len[b];
    float m = -1e30f;
    for (int tt = tid; tt < sl; tt += 256) m = fmaxf(m, a.en[tt]);
    a.red[tid] = m; __syncthreads();
    for (int o = 128; o > 0; o >>= 1) {
        if (tid < o) a.red[tid] = fmaxf(a.red[tid], a.red[tid + o]);
        __syncthreads();
    }
    m = a.red[0]; __syncthreads();
    float ssum = 0.f;
    for (int tt = tid; tt < sl; tt += 256) { float e = expf(a.en[tt] - m); a.en[tt] = e; ssum += e; }
    a.red[tid] = ssum; __syncthreads();
    for (int o = 128; o > 0; o >>= 1) {
        if (tid < o) a.red[tid] += a.red[tid + o];
        __syncthreads();
    }
    float inv = 1.0f / a.red[0];
    for (int tt = tid; tt < TT; tt += 256)
        g_attn[b * TT + tt] = (tt < sl) ? a.en[tt] * inv : 0.f;
}

// split-T ctx partial: job = (b, quarter); fp16 streaming loads of lf.
__device__ void ctx_job(SATT& a, const Params& p, int job, int t) {
    int b = job >> 2, q = job & 3;
    int tid = threadIdx.x;
    int sl = p.state_len[b];
    int tbeg = (q * sl) >> 2, tend = ((q + 1) * sl) >> 2;
    int n = tend - tbeg;
    for (int i = tid; i < n; i += 256) a.en[i] = g_attn[b * TT + tbeg + i];
    __syncthreads();
    const __half* lfb = g_lf16 + ((size_t)b * TT + tbeg) * EE + tid * 4;
    float4 acc = make_float4(0.f, 0.f, 0.f, 0.f);
    int i = 0;
    for (; i + 8 <= n; i += 8) {
        uint2 u[8];
        float wv[8];
#pragma unroll
        for (int v = 0; v < 8; v++) u[v] = __ldcs((const uint2*)(lfb + (size_t)(i + v) * EE));
#pragma unroll
        for (int v = 0; v < 8; v++) wv[v] = a.en[i + v];
#pragma unroll
        for (int v = 0; v < 8; v++) {
            float2 f0 = __half22float2(*(__half2*)&u[v].x);
            float2 f1 = __half22float2(*(__half2*)&u[v].y);
            acc.x += wv[v] * f0.x; acc.y += wv[v] * f0.y;
            acc.z += wv[v] * f1.x; acc.w += wv[v] * f1.y;
        }
    }
    for (; i < n; i++) {
        uint2 u = __ldcs((const uint2*)(lfb + (size_t)i * EE));
        float wv = a.en[i];
        float2 f0 = __half22float2(*(__half2*)&u.x);
        float2 f1 = __half22float2(*(__half2*)&u.y);
        acc.x += wv * f0.x; acc.y += wv * f0.y;
        acc.z += wv * f1.x; acc.w += wv * f1.y;
    }
    *(float4*)&g_ctxp[t & 1][q][b * EE + tid * 4] = acc;
}

__device__ __forceinline__ void logits_reduce(const Params& p, int tt, int gid0, int nthr) {
    for (int i = gid0; i < BB * (VV / 4); i += nthr) {
        int b = i / (VV / 4), v = (i - b * (VV / 4)) * 4;
        float4 s = *(const float4*)&p.bc[v];
#pragma unroll
        for (int z = 0; z < LSPLIT; z++) {
            float4 q = *(const float4*)&g_lp[(size_t)(z * BB + b) * VV + v];
            s.x += q.x; s.y += q.y; s.z += q.z; s.w += q.w;
        }
        *(float4*)&p.out[((size_t)b * LL + tt) * VV + v] = s;
    }
}

#define POOL(ci, njobs, BODY)                                           \
    for (;;) {                                                          \
        __syncthreads();                                                \
        if (threadIdx.x == 0) s_job = (int)atomicAdd(&g_jq[ci], 1u);    \
        __syncthreads();                                                \
        int job = s_job;                                                \
        if (job >= (njobs)) break;                                      \
        BODY;                                                           \
    }

__global__ void __launch_bounds__(256, 2) decoder_kernel(Params p) {
    __shared__ Smem sm;
    __shared__ int s_job;
    const unsigned nblk = p.nblk;
    int tid = threadIdx.x;
    int gid0 = blockIdx.x * 256 + tid;
    int nthr = (int)nblk * 256;

    // phase 0: zero state + transpose gates W + fp16 listener + encoder projection
    for (int i = gid0; i < BB * DD; i += nthr) { g_h[1][i] = 0.f; g_c[i] = 0.f; }
    for (int i = gid0; i < 4 * BB * EE; i += nthr) ((float*)g_ctxp[1])[i] = 0.f;
    for (size_t i = gid0; i < (size_t)KG * NG; i += (size_t)nthr) {
        int k = (int)(i / NG), j = (int)(i - (size_t)k * NG);
        g_WT[i] = (k < KI) ? p.W_ih[(size_t)j * KI + k]
                           : p.W_hh[(size_t)j * DD + (k - KI)];
    }
    for (size_t i = gid0; i < (size_t)BB * TT * EE / 4; i += (size_t)nthr) {
        float4 v = *(const float4*)&p.lf[i * 4];
        __half2* o = (__half2*)&g_lf16[i * 4];
        o[0] = __floats2half2_rn(v.x, v.y);
        o[1] = __floats2half2_rn(v.z, v.w);
    }
    POOL(0, NJ_COMP, comp_tile(sm.g, p, job))
    gsync(nblk, 1);

    for (int t = 0; t < LL; t++) {
        int pp = (t + 1) & 1;
        // A: reduce logits(t-2) + gates(t)
        if (t >= 2) logits_reduce(p, t - 2, gid0, nthr);
        POOL(0, NJ_GATES, gates_tile(sm.g, p, job, t, pp))
        gsync(nblk, 1);
        // BC: lstm+attn (blocks 0..63) overlapped with logits(t-1)
        if (blockIdx.x < BB) lstm_attn(sm.a, p, blockIdx.x, t);
        if (t >= 1) { POOL(1, NJ_LOGITS, logits_tile(sm.g, p, job, pp)) }
        gsync(nblk, 0);
        // D: ctx(t) partials + leftover logits(t-1)
        POOL(2, NJ_CTX, ctx_job(sm.a, p, job, t))
        if (t >= 1) { POOL(1, NJ_LOGITS, logits_tile(sm.g, p, job, pp)) }
        gsync(nblk, 2 | 4);
    }
    logits_reduce(p, LL - 2, gid0, nthr);
    gsync(nblk, 0);
    POOL(1, NJ_LOGITS, logits_tile(sm.g, p, job, (LL - 1) & 1))
    gsync(nblk, 2);
    logits_reduce(p, LL - 1, gid0, nthr);
}

extern "C" void kernel_launch(void* const* d_in, const int* in_sizes, int n_in,
                              void* d_out, int out_size) {
    Params p;
    p.lf        = (const float*)d_in[0];
    p.state_len = (const int*)  d_in[1];
    p.tokens    = (const int*)  d_in[2];
    p.emb       = (const float*)d_in[3];
    p.W_ih      = (const float*)d_in[4];
    p.W_hh      = (const float*)d_in[5];
    p.b_ih      = (const float*)d_in[6];
    p.b_hh      = (const float*)d_in[7];
    p.phi       = (const float*)d_in[8];
    p.psi       = (const float*)d_in[9];
    p.bpsi      = (const float*)d_in[10];
    p.Wc        = (const float*)d_in[11];
    p.bc        = (const float*)d_in[12];
    p.out       = (float*)d_out;

    int dev = 0;
    cudaGetDevice(&dev);
    int sms = 0;
    cudaDeviceGetAttribute(&sms, cudaDevAttrMultiProcessorCount, dev);
    int occ = 0;
    cudaOccupancyMaxActiveBlocksPerMultiprocessor(&occ, decoder_kernel, 256, 0);
    if (occ < 1) occ = 1;
    if (occ > 2) occ = 2;
    unsigned nblk = (unsigned)(sms * occ);
    p.nblk = nblk;

    decoder_kernel<<<nblk, 256>>>(p);
}

// round 16
// speedup vs baseline: 1.0031x; 1.0031x over previous
#include <cuda_runtime.h>
#include <cuda_fp16.h>
#include <stdint.h>
#include <math.h>

#define BB 64
#define TT 800
#define EE 1024
#define DD 1024
#define DEDIM 256
#define AA 256
#define VV 8000
#define LL 150
#define KI 1280          // DE + E
#define NG 4096          // 4*D
#define KC 2048          // D + E
#define KG 2304          // DE + E + D
#define GSPLIT 8
#define LSPLIT 8
#define GCH (KG / GSPLIT / 16)            // 18 chunks / gates job
#define LCH (KC / LSPLIT / 16)            // 16 chunks / logits job
#define NJ_GATES (GSPLIT * (NG / 128))    // 256
#define NJ_LOGITS (LSPLIT * 63)           // 504
#define NJ_CTX 256
#define NJ_COMP 1600
#define NST 3                              // cp.async pipeline stages

// ---------------- device scratch (static, allocation-free) ----------------
__device__ __align__(128) __half g_comp16[(size_t)BB * TT * AA];  // 26.2 MB fp16 comp_enc
__device__ __align__(128) __half g_lf16[(size_t)BB * TT * EE];    // 104.9 MB fp16 listener
__device__ __align__(128) float g_WT[(size_t)KG * NG];            // 37.7 MB k-major gates W
__device__ __align__(128) float g_h[2][BB * DD];
__device__ __align__(128) float g_c[BB * DD];
__device__ __align__(128) float g_ctxp[2][4][BB * EE];            // split-T ctx partials
__device__ __align__(128) float g_gp[GSPLIT * BB * NG];
__device__ __align__(128) float g_lp[LSPLIT * BB * VV];
__device__ __align__(128) float g_attn[BB * TT];
__device__ unsigned g_cnt = 0;
__device__ unsigned g_gen = 0;
__device__ unsigned g_jq[3] = {0, 0, 0};

struct Params {
    const float *lf, *emb, *W_ih, *W_hh, *b_ih, *b_hh, *phi, *psi, *bpsi, *Wc, *bc;
    const int *state_len, *tokens;
    float* out;
    unsigned nblk;
};

struct SGEM { float As[NST][16][68]; float Bs[NST][16][132]; };   // 38.4 KB
struct SATT { float hs[DD]; float qs[AA]; float en[TT]; float red[256]; };
union Smem { SGEM g; SATT a; };

__device__ __forceinline__ float sigf(float x) { return 1.0f / (1.0f + expf(-x)); }

__device__ __forceinline__ void cp16(uint32_t d, const void* s) {
    asm volatile("cp.async.cg.shared.global [%0], [%1], 16;" :: "r"(d), "l"(s));
}
#define CP_COMMIT() asm volatile("cp.async.commit_group;")
#define CP_WAIT1()  asm volatile("cp.async.wait_group 1;")

// ---- packed fp32x2 FMA helpers (bitwise == 2x scalar FFMA rn) ----
__device__ __forceinline__ void fma2(unsigned long long& acc, unsigned long long a,
                                     unsigned long long b) {
    asm("fma.rn.f32x2 %0, %1, %2, %0;" : "+l"(acc) : "l"(a), "l"(b));
}
__device__ __forceinline__ unsigned long long dupf(float x) {
    unsigned long long r;
    asm("mov.b64 %0, {%1, %1};" : "=l"(r) : "f"(x));
    return r;
}
__device__ __forceinline__ float2 unpk(unsigned long long v) {
    float2 r;
    asm("mov.b64 {%0, %1}, %2;" : "=f"(r.x), "=f"(r.y) : "l"(v));
    return r;
}

// ---------------- grid barrier; releaser resets selected job counters ------
__device__ __forceinline__ void gsync(unsigned nblk, int rmask) {
    __threadfence();
    __syncthreads();
    if (threadIdx.x == 0) {
        unsigned gen = *(volatile unsigned*)&g_gen;
        if (atomicAdd(&g_cnt, 1u) == nblk - 1u) {
            g_cnt = 0;
            if (rmask & 1) g_jq[0] = 0;
            if (rmask & 2) g_jq[1] = 0;
            if (rmask & 4) g_jq[2] = 0;
            __threadfence();
            atomicAdd(&g_gen, 1u);
        } else {
            while (*(volatile unsigned*)&g_gen == gen) { __nanosleep(32); }
        }
    }
    __syncthreads();
    __threadfence();
}

// ---- ctx read = sum of 4 split-T partials (L2-resident, deterministic order) ----
__device__ __forceinline__ float4 ctx_sum(int par, int idx) {
    float4 a = *(const float4*)&g_ctxp[par][0][idx];
    float4 b = *(const float4*)&g_ctxp[par][1][idx];
    float4 c = *(const float4*)&g_ctxp[par][2][idx];
    float4 d = *(const float4*)&g_ctxp[par][3][idx];
    return make_float4((a.x + b.x) + (c.x + d.x), (a.y + b.y) + (c.y + d.y),
                       (a.z + b.z) + (c.z + d.z), (a.w + b.w) + (c.w + d.w));
}

// ------------- 64x128 tile core, packed f32x2: 4 rows x 4 col-pairs --------
__device__ __forceinline__ void mma16(const float (*As)[68], const float (*Bs)[132],
                                      unsigned long long (&acc)[4][4], int tx, int ty) {
#pragma unroll
    for (int kk = 0; kk < 16; kk++) {
        float4 a = *(const float4*)&As[kk][ty * 4];
        ulonglong2 bl = *(const ulonglong2*)&Bs[kk][tx * 4];
        ulonglong2 bh = *(const ulonglong2*)&Bs[kk][64 + tx * 4];
        unsigned long long ap[4] = {dupf(a.x), dupf(a.y), dupf(a.z), dupf(a.w)};
#pragma unroll
        for (int i = 0; i < 4; i++) {
            fma2(acc[i][0], ap[i], bl.x);
            fma2(acc[i][1], ap[i], bl.y);
            fma2(acc[i][2], ap[i], bh.x);
            fma2(acc[i][3], ap[i], bh.y);
        }
    }
}

// ================= 3-stage pipelined tile bodies =================

__device__ __forceinline__ float4 ld_gates_a(const Params& p, int par, int am,
                                             int tok, int k) {
    if (k < DEDIM) return *(const float4*)&p.emb[(size_t)tok * DEDIM + k];
    if (k < KI)    return ctx_sum(par, am * EE + (k - DEDIM));
    return *(const float4*)&g_h[par][am * DD + (k - KI)];
}

__device__ __forceinline__ void stA(float (*As)[68], int akq, int am, float4 v) {
    As[akq + 0][am] = v.x; As[akq + 1][am] = v.y;
    As[akq + 2][am] = v.z; As[akq + 3][am] = v.w;
}

__device__ void gates_tile(SGEM& s, const Params& p, int job, int t, int pp) {
    int z = job >> 5, nt = job & 31;
    int j0 = nt * 128;
    int kbeg = z * (KG / GSPLIT);
    int tid = threadIdx.x, tx = tid & 15, ty = tid >> 4;
    int am = tid >> 2, akq = (tid & 3) * 4;
    int bk0 = tid >> 5, bn0 = (tid & 31) * 4;
    int tok = p.tokens[am * LL + t];
    uint32_t sB[NST];
#pragma unroll
    for (int u = 0; u < NST; u++)
        sB[u] = (uint32_t)__cvta_generic_to_shared(&s.Bs[u][bk0][bn0]);
    const size_t brow8 = (size_t)8 * NG;
    unsigned long long acc[4][4] = {};
#pragma unroll
    for (int u = 0; u < 2; u++) {
        stA(s.As[u], akq, am, ld_gates_a(p, pp, am, tok, kbeg + u * 16 + akq));
        const float* w = &g_WT[(size_t)(kbeg + u * 16 + bk0) * NG + j0 + bn0];
        cp16(sB[u], w);
        cp16(sB[u] + 8 * 132 * 4, w + brow8);
        CP_COMMIT();
    }
    float4 areg = ld_gates_a(p, pp, am, tok, kbeg + 32 + akq);
    for (int kt = 0; kt < GCH; kt++) {
        int cur = kt % NST, nx2 = (kt + 2) % NST;
        CP_WAIT1();
        __syncthreads();
        if (kt + 2 < GCH) {
            stA(s.As[nx2], akq, am, areg);
            const float* w = &g_WT[(size_t)(kbeg + (kt + 2) * 16 + bk0) * NG + j0 + bn0];
            cp16(sB[nx2], w);
            cp16(sB[nx2] + 8 * 132 * 4, w + brow8);
        }
        CP_COMMIT();
        if (kt + 3 < GCH)
            areg = ld_gates_a(p, pp, am, tok, kbeg + (kt + 3) * 16 + akq);
        mma16(s.As[cur], s.Bs[cur], acc, tx, ty);
    }
#pragma unroll
    for (int i = 0; i < 4; i++) {
        int b = ty * 4 + i;
        float* dst = &g_gp[(size_t)(z * BB + b) * NG + j0];
        float2 p0 = unpk(acc[i][0]), p1 = unpk(acc[i][1]);
        float2 p2 = unpk(acc[i][2]), p3 = unpk(acc[i][3]);
        *(float4*)(dst + tx * 4)      = make_float4(p0.x, p0.y, p1.x, p1.y);
        *(float4*)(dst + 64 + tx * 4) = make_float4(p2.x, p2.y, p3.x, p3.y);
    }
}

__device__ __forceinline__ float4 ld_logits_a(int par, int am, int k) {
    if (k < DD) return *(const float4*)&g_h[par][am * DD + k];
    return ctx_sum(par, am * EE + (k - DD));
}

__device__ void logits_tile(SGEM& s, const Params& p, int job, int pl) {
    int z = job / 63;
    int nt = job - z * 63;
    int v0 = nt * 128;
    bool full = (nt < 62);
    int kbeg = z * (KC / LSPLIT);
    int tid = threadIdx.x, tx = tid & 15, ty = tid >> 4;
    int am = tid >> 2, akq = (tid & 3) * 4;
    int bk0 = tid >> 5, bn0 = (tid & 31) * 4;
    int c0 = v0 + bn0;        if (c0 > VV - 4) c0 = VV - 4;   // clamp: only feeds discarded cols
    uint32_t sB[NST];
#pragma unroll
    for (int u = 0; u < NST; u++)
        sB[u] = (uint32_t)__cvta_generic_to_shared(&s.Bs[u][bk0][bn0]);
    unsigned long long acc[4][4] = {};
#pragma unroll
    for (int u = 0; u < 2; u++) {
        stA(s.As[u], akq, am, ld_logits_a(pl, am, kbeg + u * 16 + akq));
        const float* w0 = &p.Wc[(size_t)(kbeg + u * 16 + bk0) * VV];
        cp16(sB[u], w0 + c0);
        cp16(sB[u] + 8 * 132 * 4, w0 + (size_t)8 * VV + c0);
        CP_COMMIT();
    }
    float4 areg = ld_logits_a(pl, am, kbeg + 32 + akq);
    for (int kt = 0; kt < LCH; kt++) {
        int cur = kt % NST, nx2 = (kt + 2) % NST;
        CP_WAIT1();
        __syncthreads();
        if (kt + 2 < LCH) {
            stA(s.As[nx2], akq, am, areg);
            const float* w0 = &p.Wc[(size_t)(kbeg + (kt + 2) * 16 + bk0) * VV];
            cp16(sB[nx2], w0 + c0);
            cp16(sB[nx2] + 8 * 132 * 4, w0 + (size_t)8 * VV + c0);
        }
        CP_COMMIT();
        if (kt + 3 < LCH)
            areg = ld_logits_a(pl, am, kbeg + (kt + 3) * 16 + akq);
        mma16(s.As[cur], s.Bs[cur], acc, tx, ty);
    }
#pragma unroll
    for (int i = 0; i < 4; i++) {
        int b = ty * 4 + i;
        float* dst = &g_lp[(size_t)(z * BB + b) * VV + v0];
        float2 p0 = unpk(acc[i][0]), p1 = unpk(acc[i][1]);
        *(float4*)(dst + tx * 4) = make_float4(p0.x, p0.y, p1.x, p1.y);
        if (full) {
            float2 p2 = unpk(acc[i][2]), p3 = unpk(acc[i][3]);
            *(float4*)(dst + 64 + tx * 4) = make_float4(p2.x, p2.y, p3.x, p3.y);
        }
    }
}

__device__ void comp_tile(SGEM& s, const Params& p, int job) {
    int nt = job & 1, mt = job >> 1;
    int m0 = mt * 64, n0 = nt * 128;
    int tid = threadIdx.x, tx = tid & 15, ty = tid >> 4;
    int am = tid >> 2, akq = (tid & 3) * 4;
    int bk0 = tid >> 5, bn0 = (tid & 31) * 4;
    uint32_t sB[NST];
#pragma unroll
    for (int u = 0; u < NST; u++)
        sB[u] = (uint32_t)__cvta_generic_to_shared(&s.Bs[u][bk0][bn0]);
    const float* arow = p.lf + (size_t)(m0 + am) * EE;
    unsigned long long acc[4][4] = {};
#pragma unroll
    for (int u = 0; u < 2; u++) {
        stA(s.As[u], akq, am, *(const float4*)&arow[u * 16 + akq]);
        const float* w = &p.psi[(size_t)(u * 16 + bk0) * AA + n0 + bn0];
        cp16(sB[u], w);
        cp16(sB[u] + 8 * 132 * 4, w + (size_t)8 * AA);
        CP_COMMIT();
    }
    float4 areg = *(const float4*)&arow[32 + akq];
    const int NCH = EE / 16;
    for (int kt = 0; kt < NCH; kt++) {
        int cur = kt % NST, nx2 = (kt + 2) % NST;
        CP_WAIT1();
        __syncthreads();
        if (kt + 2 < NCH) {
            stA(s.As[nx2], akq, am, areg);
            const float* w = &p.psi[(size_t)((kt + 2) * 16 + bk0) * AA + n0 + bn0];
            cp16(sB[nx2], w);
            cp16(sB[nx2] + 8 * 132 * 4, w + (size_t)8 * AA);
        }
        CP_COMMIT();
        if (kt + 3 < NCH) areg = *(const float4*)&arow[(kt + 3) * 16 + akq];
        mma16(s.As[cur], s.Bs[cur], acc, tx, ty);
    }
#pragma unroll
    for (int i = 0; i < 4; i++) {
        int m = m0 + ty * 4 + i;
        int nA = n0 + tx * 4, nB = n0 + 64 + tx * 4;
        float2 p0 = unpk(acc[i][0]), p1 = unpk(acc[i][1]);
        float2 p2 = unpk(acc[i][2]), p3 = unpk(acc[i][3]);
        __half2* oA = (__half2*)&g_comp16[(size_t)m * AA + nA];
        __half2* oB = (__half2*)&g_comp16[(size_t)m * AA + nB];
        oA[0] = __floats2half2_rn(tanhf(p0.x + p.bpsi[nA + 0]), tanhf(p0.y + p.bpsi[nA + 1]));
        oA[1] = __floats2half2_rn(tanhf(p1.x + p.bpsi[nA + 2]), tanhf(p1.y + p.bpsi[nA + 3]));
        oB[0] = __floats2half2_rn(tanhf(p2.x + p.bpsi[nB + 0]), tanhf(p2.y + p.bpsi[nB + 1]));
        oB[1] = __floats2half2_rn(tanhf(p3.x + p.bpsi[nB + 2]), tanhf(p3.y + p.bpsi[nB + 3]));
    }
}

// lstm + q + energy + masked softmax for batch row b (one block)
__device__ void lstm_attn(SATT& a, const Params& p, int b, int t) {
    int tid = threadIdx.x;
    int pt = t & 1;
#pragma unroll
    for (int i = 0; i < 4; i++) {
        int d = tid + i * 256;
        int g = b * DD + d;
        float gv[4];
#pragma unroll
        for (int q = 0; q < 4; q++) {
            int j = q * DD + d;
            float s = p.b_ih[j] + p.b_hh[j];
#pragma unroll
            for (int z = 0; z < GSPLIT; z++) s += g_gp[(size_t)(z * BB + b) * NG + j];
            gv[q] = s;
        }
        float cn = sigf(gv[1]) * g_c[g] + sigf(gv[0]) * tanhf(gv[2]);
        g_c[g] = cn;
        float hn = sigf(gv[3]) * tanhf(cn);
        g_h[pt][g] = hn;
        a.hs[d] = hn;
    }
    __syncthreads();
    {
        float acc0 = 0.f, acc1 = 0.f, acc2 = 0.f, acc3 = 0.f;
        const float* ph = p.phi + tid;
        for (int k = 0; k < DD; k += 4) {
            acc0 += a.hs[k]     * ph[0];
            acc1 += a.hs[k + 1] * ph[AA];
            acc2 += a.hs[k + 2] * ph[2 * AA];
            acc3 += a.hs[k + 3] * ph[3 * AA];
            ph += 4 * AA;
        }
        a.qs[tid] = tanhf((acc0 + acc1) + (acc2 + acc3));
    }
    __syncthreads();
    int w = tid >> 5, lane = tid & 31;
    float4 q0 = *(const float4*)&a.qs[lane * 8];
    float4 q1 = *(const float4*)&a.qs[lane * 8 + 4];
    for (int tb = w; tb < TT; tb += 16) {
        int ta = tb, tc = tb + 8;
        uint4 ua = *(const uint4*)(g_comp16 + ((size_t)b * TT + ta) * AA + lane * 8);
        uint4 uc = *(const uint4*)(g_comp16 + ((size_t)b * TT + tc) * AA + lane * 8);
        float2 x0 = __half22float2(*(__half2*)&ua.x);
        float2 x1 = __half22float2(*(__half2*)&ua.y);
        float2 x2 = __half22float2(*(__half2*)&ua.z);
        float2 x3 = __half22float2(*(__half2*)&ua.w);
        float2 y0 = __half22float2(*(__half2*)&uc.x);
        float2 y1 = __half22float2(*(__half2*)&uc.y);
        float2 y2 = __half22float2(*(__half2*)&uc.z);
        float2 y3 = __half22float2(*(__half2*)&uc.w);
        float sa = x0.x * q0.x + x0.y * q0.y + x1.x * q0.z + x1.y * q0.w
                 + x2.x * q1.x + x2.y * q1.y + x3.x * q1.z + x3.y * q1.w;
        float sc = y0.x * q0.x + y0.y * q0.y + y1.x * q0.z + y1.y * q0.w
                 + y2.x * q1.x + y2.y * q1.y + y3.x * q1.z + y3.y * q1.w;
#pragma unroll
        for (int o = 16; o > 0; o >>= 1) {
            sa += __shfl_down_sync(0xffffffffu, sa, o);
            sc += __shfl_down_sync(0xffffffffu, sc, o);
        }
        if (lane == 0) { a.en[ta] = 2.0f * sa; a.en[tc] = 2.0f * sc; }
    }
    __syncthreads();
    int sl = p.state_len[b];
    float m = -1e30f;
    for (int tt = tid; tt < sl; tt += 256) m = fmaxf(m, a.en[tt]);
    a.red[tid] = m; __syncthreads();
    for (int o = 128; o > 0; o >>= 1) {
        if (tid < o) a.red[tid] = fmaxf(a.red[tid], a.red[tid + o]);
        __syncthreads();
    }
    m = a.red[0]; __syncthreads();
    float ssum = 0.f;
    for (int tt = tid; tt < sl; tt += 256) { float e = expf(a.en[tt] - m); a.en[tt] = e; ssum += e; }
    a.red[tid] = ssum; __syncthreads();
    for (int o = 128; o > 0; o >>= 1) {
        if (tid < o) a.red[tid] += a.red[tid + o];
        __syncthreads();
    }
    float inv = 1.0f / a.red[0];
    for (int tt = tid; tt < TT; tt += 256)
        g_attn[b * TT + tt] = (tt < sl) ? a.en[tt] * inv : 0.f;
}

// split-T ctx partial: job = (b, quarter); fp16 streaming loads of lf.
__device__ void ctx_job(SATT& a, const Params& p, int job, int t) {
    int b = job >> 2, q = job & 3;
    int tid = threadIdx.x;
    int sl = p.state_len[b];
    int tbeg = (q * sl) >> 2, tend = ((q + 1) * sl) >> 2;
    int n = tend - tbeg;
    for (int i = tid; i < n; i += 256) a.en[i] = g_attn[b * TT + tbeg + i];
    __syncthreads();
    const __half* lfb = g_lf16 + ((size_t)b * TT + tbeg) * EE + tid * 4;
    float4 acc = make_float4(0.f, 0.f, 0.f, 0.f);
    int i = 0;
    for (; i + 8 <= n; i += 8) {
        uint2 u[8];
        float wv[8];
#pragma unroll
        for (int v = 0; v < 8; v++) u[v] = __ldcs((const uint2*)(lfb + (size_t)(i + v) * EE));
#pragma unroll
        for (int v = 0; v < 8; v++) wv[v] = a.en[i + v];
#pragma unroll
        for (int v = 0; v < 8; v++) {
            float2 f0 = __half22float2(*(__half2*)&u[v].x);
            float2 f1 = __half22float2(*(__half2*)&u[v].y);
            acc.x += wv[v] * f0.x; acc.y += wv[v] * f0.y;
            acc.z += wv[v] * f1.x; acc.w += wv[v] * f1.y;
        }
    }
    for (; i < n; i++) {
        uint2 u = __ldcs((const uint2*)(lfb + (size_t)i * EE));
        float wv = a.en[i];
        float2 f0 = __half22float2(*(__half2*)&u.x);
        float2 f1 = __half22float2(*(__half2*)&u.y);
        acc.x += wv * f0.x; acc.y += wv * f0.y;
        acc.z += wv * f1.x; acc.w += wv * f1.y;
    }
    *(float4*)&g_ctxp[t & 1][q][b * EE + tid * 4] = acc;
}

__device__ __forceinline__ void logits_reduce(const Params& p, int tt, int gid0, int nthr) {
    for (int i = gid0; i < BB * (VV / 4); i += nthr) {
        int b = i / (VV / 4), v = (i - b * (VV / 4)) * 4;
        float4 s = *(const float4*)&p.bc[v];
#pragma unroll
        for (int z = 0; z < LSPLIT; z++) {
            float4 q = *(const float4*)&g_lp[(size_t)(z * BB + b) * VV + v];
            s.x += q.x; s.y += q.y; s.z += q.z; s.w += q.w;
        }
        *(float4*)&p.out[((size_t)b * LL + tt) * VV + v] = s;
    }
}

#define POOL(ci, njobs, BODY)                                           \
    for (;;) {                                                          \
        __syncthreads();                                                \
        if (threadIdx.x == 0) s_job = (int)atomicAdd(&g_jq[ci], 1u);    \
        __syncthreads();                                                \
        int job = s_job;                                                \
        if (job >= (njobs)) break;                                      \
        BODY;                                                           \
    }

__global__ void __launch_bounds__(256, 2) decoder_kernel(Params p) {
    __shared__ Smem sm;
    __shared__ int s_job;
    const unsigned nblk = p.nblk;
    int tid = threadIdx.x;
    int gid0 = blockIdx.x * 256 + tid;
    int nthr = (int)nblk * 256;

    // phase 0: zero state + transpose gates W + fp16 listener + encoder projection
    for (int i = gid0; i < BB * DD; i += nthr) { g_h[1][i] = 0.f; g_c[i] = 0.f; }
    for (int i = gid0; i < 4 * BB * EE; i += nthr) ((float*)g_ctxp[1])[i] = 0.f;
    for (size_t i = gid0; i < (size_t)KG * NG; i += (size_t)nthr) {
        int k = (int)(i / NG), j = (int)(i - (size_t)k * NG);
        g_WT[i] = (k < KI) ? p.W_ih[(size_t)j * KI + k]
                           : p.W_hh[(size_t)j * DD + (k - KI)];
    }
    for (size_t i = gid0; i < (size_t)BB * TT * EE / 4; i += (size_t)nthr) {
        float4 v = *(const float4*)&p.lf[i * 4];
        __half2* o = (__half2*)&g_lf16[i * 4];
        o[0] = __floats2half2_rn(v.x, v.y);
        o[1] = __floats2half2_rn(v.z, v.w);
    }
    POOL(0, NJ_COMP, comp_tile(sm.g, p, job))
    gsync(nblk, 1);

    for (int t = 0; t < LL; t++) {
        int pp = (t + 1) & 1;
        // A: reduce logits(t-2) + gates(t)
        if (t >= 2) logits_reduce(p, t - 2, gid0, nthr);
        POOL(0, NJ_GATES, gates_tile(sm.g, p, job, t, pp))
        gsync(nblk, 1);
        // BC: lstm+attn (blocks 0..63) overlapped with logits(t-1)
        if (blockIdx.x < BB) lstm_attn(sm.a, p, blockIdx.x, t);
        if (t >= 1) { POOL(1, NJ_LOGITS, logits_tile(sm.g, p, job, pp)) }
        gsync(nblk, 0);
        // D: ctx(t) partials + leftover logits(t-1)
        POOL(2, NJ_CTX, ctx_job(sm.a, p, job, t))
        if (t >= 1) { POOL(1, NJ_LOGITS, logits_tile(sm.g, p, job, pp)) }
        gsync(nblk, 2 | 4);
    }
    logits_reduce(p, LL - 2, gid0, nthr);
    gsync(nblk, 0);
    POOL(1, NJ_LOGITS, logits_tile(sm.g, p, job, (LL - 1) & 1))
    gsync(nblk, 2);
    logits_reduce(p, LL - 1, gid0, nthr);
}

extern "C" void kernel_launch(void* const* d_in, const int* in_sizes, int n_in,
                              void* d_out, int out_size) {
    Params p;
    p.lf        = (const float*)d_in[0];
    p.state_len = (const int*)  d_in[1];
    p.tokens    = (const int*)  d_in[2];
    p.emb       = (const float*)d_in[3];
    p.W_ih      = (const float*)d_in[4];
    p.W_hh      = (const float*)d_in[5];
    p.b_ih      = (const float*)d_in[6];
    p.b_hh      = (const float*)d_in[7];
    p.phi       = (const float*)d_in[8];
    p.psi       = (const float*)d_in[9];
    p.bpsi      = (const float*)d_in[10];
    p.Wc        = (const float*)d_in[11];
    p.bc        = (const float*)d_in[12];
    p.out       = (float*)d_out;

    int dev = 0;
    cudaGetDevice(&dev);
    int sms = 0;
    cudaDeviceGetAttribute(&sms, cudaDevAttrMultiProcessorCount, dev);
    int occ = 0;
    cudaOccupancyMaxActiveBlocksPerMultiprocessor(&occ, decoder_kernel, 256, 0);
    if (occ < 1) occ = 1;
    if (occ > 2) occ = 2;
    unsigned nblk = (unsigned)(sms * occ);
    p.nblk = nblk;

    decoder_kernel<<<nblk, 256>>>(p);
}